// round 3
// baseline (speedup 1.0000x reference)
#include <cuda_runtime.h>
#include <math.h>

// Problem dims
#define H   256
#define H2  512
#define H3  768
#define B   64
#define L   2048
#define V   32000
#define NCH 32              // l-chunks of 64

typedef unsigned long long ull;

// ---------------- scratch (device globals; no allocation allowed) ----------------
__device__ __align__(16) float g_w2[H2];        // attn_W^T @ flatten
__device__ __align__(16) float g_ehb[B];        // e_h[b] + bias_term
__device__ __align__(16) float g_emb[B * H];    // embedded
__device__ __align__(16) float g_attn[B * L];   // energies -> weights (in place)
__device__ __align__(16) float g_ctx[B * H];    // context
__device__ __align__(16) float g_pm[B * NCH];   // chunk max
__device__ __align__(16) float g_ps[B * NCH];   // chunk expsum
__device__ __align__(16) float g_ctxp[B * NCH * H]; // partial contexts (2MB)
__device__ __align__(16) float g_gi[B * H3];
__device__ __align__(16) float g_gh[B * H3];
__device__ __align__(16) float g_yT[H2 * B];    // y transposed: [k][b]
__device__ __align__(16) float g_logits[B * V];
__device__ __align__(16) float g_lpm[B * 256];  // logits partial max per (b, k7-block)
__device__ __align__(16) float g_lps[B * 256];  // logits partial expsum
__device__ __align__(16) float g_lse[B];

// ---------------- K1: w2, bias, e_h+bias, embedding gather -----------------------
__global__ void k1_prep(const float* __restrict__ attn_W,
                        const float* __restrict__ attn_b,
                        const float* __restrict__ flatten,
                        const float* __restrict__ hidden,
                        const int*   __restrict__ input,
                        const float* __restrict__ emb_table)
{
    __shared__ float s_f[H];
    __shared__ float s_wh[H];
    __shared__ float red[512];
    int tid = threadIdx.x;                      // 512 threads

    if (tid < H) s_f[tid] = flatten[tid];
    __syncthreads();

    // w2[j] = sum_i attn_W[i, j] * f[i]
    float acc = 0.f;
    #pragma unroll 8
    for (int i = 0; i < H; i++) acc += attn_W[i * H2 + tid] * s_f[i];
    g_w2[tid] = acc;
    if (tid < H) s_wh[tid] = acc;

    // bias = f . attn_b
    red[tid] = (tid < H) ? s_f[tid] * attn_b[tid] : 0.f;
    __syncthreads();
    for (int s = 256; s > 0; s >>= 1) {
        if (tid < s) red[tid] += red[tid + s];
        __syncthreads();
    }
    float bias = red[0];

    // e_h[b] = h[b] . w2[:H]; store e_h + bias
    int wid = tid >> 5, lane = tid & 31;
    #pragma unroll
    for (int i = 0; i < 4; i++) {
        int b = wid * 4 + i;
        float a = 0.f;
        #pragma unroll
        for (int c = 0; c < 8; c++) {
            int k = c * 32 + lane;
            a += hidden[b * H + k] * s_wh[k];
        }
        #pragma unroll
        for (int o = 16; o > 0; o >>= 1) a += __shfl_down_sync(0xffffffffu, a, o);
        if (lane == 0) g_ehb[b] = a + bias;
    }

    // embedded gather
    for (int idx = tid; idx < B * H; idx += 512) {
        int b = idx >> 8;
        g_emb[idx] = emb_table[(size_t)input[b] * H + (idx & 255)];
    }
}

// ---------------- KA: fused energies + chunk softmax + partial context -----------
// One pass over enc. Block = (b, chunk of 64 l). smem tile 64x256.
__global__ __launch_bounds__(256) void kA_attn(const float* __restrict__ enc)
{
    extern __shared__ float sm[];
    float* tile = sm;                // 64*256
    float* s_w2 = sm + 64 * H;       // 256
    float* s_e  = s_w2 + H;          // 64
    float* s_w  = s_e + 64;          // 64
    float* s_m  = s_w + 64;          // 1

    int b = blockIdx.x >> 5;
    int c = blockIdx.x & 31;
    int tid = threadIdx.x;
    int l0 = c * 64;

    s_w2[tid] = g_w2[H + tid];

    // load tile: 64 rows x 64 float4, coalesced (row stride B*H/4 = 4096 float4)
    const float4* src = (const float4*)(enc + ((size_t)l0 * B + b) * H);
    float4* t4 = (float4*)tile;
    #pragma unroll
    for (int i = 0; i < 16; i++) {
        int idx = tid + 256 * i;
        int row = idx >> 6, col = idx & 63;
        t4[row * 64 + col] = src[(size_t)row * 4096 + col];
    }
    __syncthreads();

    // energies: 8 warps x 8 l
    int wid = tid >> 5, lane = tid & 31;
    #pragma unroll
    for (int i = 0; i < 8; i++) {
        int l = wid * 8 + i;
        const float4* tr = (const float4*)(tile + l * H);
        const float4* w4 = (const float4*)s_w2;
        float4 t0 = tr[lane],      w0 = w4[lane];
        float4 t1 = tr[32 + lane], w1 = w4[32 + lane];
        float a = t0.x * w0.x + t0.y * w0.y + t0.z * w0.z + t0.w * w0.w
                + t1.x * w1.x + t1.y * w1.y + t1.z * w1.z + t1.w * w1.w;
        #pragma unroll
        for (int o = 16; o > 0; o >>= 1) a += __shfl_down_sync(0xffffffffu, a, o);
        if (lane == 0) {
            float e = a + g_ehb[b];
            s_e[l] = e;
            g_attn[b * L + l0 + l] = e;     // raw energy; normalized in kB
        }
    }
    __syncthreads();

    // chunk max
    if (wid == 0) {
        float m = fmaxf(s_e[lane], s_e[32 + lane]);
        #pragma unroll
        for (int o = 16; o > 0; o >>= 1) m = fmaxf(m, __shfl_xor_sync(0xffffffffu, m, o));
        if (lane == 0) s_m[0] = m;
    }
    __syncthreads();
    float m = s_m[0];
    if (tid < 64) s_w[tid] = __expf(s_e[tid] - m);
    __syncthreads();
    if (wid == 0) {
        float s = s_w[lane] + s_w[32 + lane];
        #pragma unroll
        for (int o = 16; o > 0; o >>= 1) s += __shfl_xor_sync(0xffffffffu, s, o);
        if (lane == 0) { g_pm[b * NCH + c] = m; g_ps[b * NCH + c] = s; }
    }

    // partial context: thread = h
    float a0 = 0.f, a1 = 0.f, a2 = 0.f, a3 = 0.f;
    #pragma unroll
    for (int l = 0; l < 64; l += 4) {
        a0 += s_w[l + 0] * tile[(l + 0) * H + tid];
        a1 += s_w[l + 1] * tile[(l + 1) * H + tid];
        a2 += s_w[l + 2] * tile[(l + 2) * H + tid];
        a3 += s_w[l + 3] * tile[(l + 3) * H + tid];
    }
    g_ctxp[(size_t)(b * NCH + c) * H + tid] = (a0 + a1) + (a2 + a3);
}

// ---------------- KB: combine chunk partials -> ctx, attn weights ----------------
__global__ void kB_combine(float* __restrict__ out_attn)
{
    __shared__ float s_scale[NCH];
    __shared__ float s_mi[2];                   // m, inv_s
    int b = blockIdx.x, tid = threadIdx.x;      // 256 threads

    if (tid < 32) {
        float mc = g_pm[b * NCH + tid];
        float sc = g_ps[b * NCH + tid];
        float m = mc;
        #pragma unroll
        for (int o = 16; o > 0; o >>= 1) m = fmaxf(m, __shfl_xor_sync(0xffffffffu, m, o));
        float sca = __expf(mc - m);
        float s = sc * sca;
        #pragma unroll
        for (int o = 16; o > 0; o >>= 1) s += __shfl_xor_sync(0xffffffffu, s, o);
        s_scale[tid] = sca;
        if (tid == 0) { s_mi[0] = m; s_mi[1] = 1.f / s; }
    }
    __syncthreads();
    float m = s_mi[0], inv = s_mi[1];

    // ctx[h] = inv * sum_c scale[c] * ctxp[c][h]
    const float* cp = g_ctxp + (size_t)b * NCH * H + tid;
    float acc = 0.f;
    #pragma unroll 8
    for (int c = 0; c < NCH; c++) acc += s_scale[c] * cp[(size_t)c * H];
    g_ctx[b * H + tid] = acc * inv;

    // attention weights
    for (int l = tid; l < L; l += 256) {
        float w = __expf(g_attn[b * L + l] - m) * inv;
        g_attn[b * L + l] = w;
        if (out_attn) out_attn[b * L + l] = w;
    }
}

// ---------------- K5: GRU matvecs, weights in registers, 8 b per warp ------------
__global__ void k5_gru(const float* __restrict__ Wih, const float* __restrict__ Whh,
                       const float* __restrict__ bih, const float* __restrict__ bhh,
                       const float* __restrict__ hidden)
{
    int gw   = (blockIdx.x * blockDim.x + threadIdx.x) >> 5;   // 0..6143
    int lane = threadIdx.x & 31;
    int j  = gw >> 3;
    int bg = gw & 7;

    const float* wi = Wih + (size_t)j * H2;
    const float* wh = Whh + (size_t)j * H;
    float wi_r[16], wh_r[8];
    #pragma unroll
    for (int c = 0; c < 16; c++) wi_r[c] = wi[c * 32 + lane];
    #pragma unroll
    for (int c = 0; c < 8; c++)  wh_r[c] = wh[c * 32 + lane];
    float bi = bih[j], bh = bhh[j];

    #pragma unroll
    for (int bb = 0; bb < 8; bb++) {
        int b = bg * 8 + bb;
        const float* xe = g_emb + b * H;
        const float* xc = g_ctx + b * H;
        const float* hh = hidden + b * H;
        float a1 = 0.f, a2 = 0.f;
        #pragma unroll
        for (int c = 0; c < 8; c++) {
            int k = c * 32 + lane;
            a1 += wi_r[c]     * xe[k];
            a1 += wi_r[8 + c] * xc[k];
            a2 += wh_r[c]     * hh[k];
        }
        #pragma unroll
        for (int o = 16; o > 0; o >>= 1) {
            a1 += __shfl_down_sync(0xffffffffu, a1, o);
            a2 += __shfl_down_sync(0xffffffffu, a2, o);
        }
        if (lane == 0) {
            g_gi[b * H3 + j] = a1 + bi;
            g_gh[b * H3 + j] = a2 + bh;
        }
    }
}

// ---------------- K6: gates + h_new + build yT[k][b] = [h_new; ctx] --------------
__global__ void k6_gates(const float* __restrict__ hidden, float* __restrict__ out_h)
{
    int idx = blockIdx.x * 256 + threadIdx.x;   // B*H threads
    int b = idx >> 8, j = idx & 255;
    float gir = g_gi[b * H3 + j],          ghr = g_gh[b * H3 + j];
    float giz = g_gi[b * H3 + H + j],      ghz = g_gh[b * H3 + H + j];
    float gin = g_gi[b * H3 + 2 * H + j],  ghn = g_gh[b * H3 + 2 * H + j];
    float r = 1.f / (1.f + __expf(-(gir + ghr)));
    float z = 1.f / (1.f + __expf(-(giz + ghz)));
    float n = tanhf(gin + r * ghn);
    float hn = (1.f - z) * n + z * hidden[idx];
    if (out_h) out_h[idx] = hn;
    g_yT[j * B + b]       = hn;
    g_yT[(H + j) * B + b] = g_ctx[idx];
}

// ---------------- K7: logits GEMM + per-block lse partials -----------------------
#define SOUT_PITCH 129
__device__ __forceinline__ ull fma2(ull a, ull x, ull c) {
    asm("fma.rn.f32x2 %0, %1, %2, %3;" : "=l"(a) : "l"(x), "l"(c), "l"(a));
    return a;
}
__device__ __forceinline__ ull pack2(float w) {
    ull r;
    asm("mov.b64 %0, {%1, %1};" : "=l"(r) : "f"(w));
    return r;
}
__device__ __forceinline__ float getc(float4 v, int c) {
    return c == 0 ? v.x : (c == 1 ? v.y : (c == 2 ? v.z : v.w));
}

__global__ __launch_bounds__(256) void k7_logits(const float* __restrict__ outW,
                                                 const float* __restrict__ outb)
{
    extern __shared__ float s_y[];              // [512][64] = 128KB
    int tid = threadIdx.x;
    {
        const float4* src = (const float4*)g_yT;
        float4* dst = (float4*)s_y;
        #pragma unroll
        for (int i = 0; i < (H2 * B / 4) / 256; i++)
            dst[tid + 256 * i] = src[tid + 256 * i];
    }
    __syncthreads();

    int tb = tid & 7;
    int tv = tid >> 3;
    int v0 = blockIdx.x * 128 + tv * 4;
    int b0 = tb * 8;

    const float4* wp0 = (const float4*)(outW + (size_t)(v0 + 0) * H2);
    const float4* wp1 = (const float4*)(outW + (size_t)(v0 + 1) * H2);
    const float4* wp2 = (const float4*)(outW + (size_t)(v0 + 2) * H2);
    const float4* wp3 = (const float4*)(outW + (size_t)(v0 + 3) * H2);

    ull acc[4][4];
    #pragma unroll
    for (int j = 0; j < 4; j++)
        #pragma unroll
        for (int p = 0; p < 4; p++) acc[j][p] = 0ull;

    #pragma unroll 2
    for (int q = 0; q < H2 / 4; q++) {
        float4 wv0 = wp0[q];
        float4 wv1 = wp1[q];
        float4 wv2 = wp2[q];
        float4 wv3 = wp3[q];
        #pragma unroll
        for (int kk = 0; kk < 4; kk++) {
            int k = q * 4 + kk;
            const ulonglong2* yp = (const ulonglong2*)(s_y + k * B + b0);
            ulonglong2 ya = yp[0];
            ulonglong2 yb = yp[1];
            ull y2[4] = { ya.x, ya.y, yb.x, yb.y };
            ull w20 = pack2(getc(wv0, kk));
            ull w21 = pack2(getc(wv1, kk));
            ull w22 = pack2(getc(wv2, kk));
            ull w23 = pack2(getc(wv3, kk));
            #pragma unroll
            for (int p = 0; p < 4; p++) {
                acc[0][p] = fma2(acc[0][p], w20, y2[p]);
                acc[1][p] = fma2(acc[1][p], w21, y2[p]);
                acc[2][p] = fma2(acc[2][p], w22, y2[p]);
                acc[3][p] = fma2(acc[3][p], w23, y2[p]);
            }
        }
    }

    __syncthreads();
    float* s_out = s_y;                         // reuse: 64*129*4 = 33KB
    float bb[4];
    #pragma unroll
    for (int j = 0; j < 4; j++) bb[j] = outb[v0 + j];
    #pragma unroll
    for (int j = 0; j < 4; j++)
        #pragma unroll
        for (int p = 0; p < 4; p++) {
            float lo = __uint_as_float((unsigned)(acc[j][p] & 0xffffffffull));
            float hi = __uint_as_float((unsigned)(acc[j][p] >> 32));
            int vl = tv * 4 + j;
            s_out[(b0 + 2 * p + 0) * SOUT_PITCH + vl] = lo + bb[j];
            s_out[(b0 + 2 * p + 1) * SOUT_PITCH + vl] = hi + bb[j];
        }
    __syncthreads();

    // copy 64 x 128 tile to g_logits, coalesced float4 stores
    #pragma unroll
    for (int it = 0; it < (B * 128 / 4) / 256; it++) {
        int i = tid + it * 256;
        int vl4 = i & 31;
        int b = i >> 5;
        const float* s = s_out + b * SOUT_PITCH + vl4 * 4;
        float4 val = make_float4(s[0], s[1], s[2], s[3]);
        *(float4*)(g_logits + (size_t)b * V + blockIdx.x * 128 + vl4 * 4) = val;
    }

    // per-(b, block) lse partials over this 128-v tile (4 threads per b)
    {
        int bq = tid >> 2, i4 = tid & 3;
        const float* r = s_out + bq * SOUT_PITCH + i4 * 32;
        float m = -INFINITY;
        #pragma unroll
        for (int j = 0; j < 32; j++) m = fmaxf(m, r[j]);
        m = fmaxf(m, __shfl_xor_sync(0xffffffffu, m, 1));
        m = fmaxf(m, __shfl_xor_sync(0xffffffffu, m, 2));
        float s = 0.f;
        #pragma unroll
        for (int j = 0; j < 32; j++) s += __expf(r[j] - m);
        s += __shfl_xor_sync(0xffffffffu, s, 1);
        s += __shfl_xor_sync(0xffffffffu, s, 2);
        if (i4 == 0) {
            g_lpm[bq * 256 + blockIdx.x] = m;
            g_lps[bq * 256 + blockIdx.x] = s;
        }
    }
}

// ---------------- K8m: merge lse partials (warp per b) ----------------------------
__global__ void k8m_merge()
{
    int b = blockIdx.x, lane = threadIdx.x;     // 32 threads
    float m = -INFINITY;
    for (int i = lane; i < 250; i += 32) m = fmaxf(m, g_lpm[b * 256 + i]);
    #pragma unroll
    for (int o = 16; o > 0; o >>= 1) m = fmaxf(m, __shfl_xor_sync(0xffffffffu, m, o));
    float s = 0.f;
    for (int i = lane; i < 250; i += 32)
        s += g_lps[b * 256 + i] * __expf(g_lpm[b * 256 + i] - m);
    #pragma unroll
    for (int o = 16; o > 0; o >>= 1) s += __shfl_xor_sync(0xffffffffu, s, o);
    if (lane == 0) g_lse[b] = m + logf(s);
}

// ---------------- K8w: out = logits - lse[b] (float4, 2000 blocks) ----------------
__global__ void k8w_write(float* __restrict__ out)
{
    int idx = blockIdx.x * 256 + threadIdx.x;   // float4 index, 512000 total
    int b = idx / (V / 4);
    float lse = g_lse[b];
    float4 v = ((const float4*)g_logits)[idx];
    v.x -= lse; v.y -= lse; v.z -= lse; v.w -= lse;
    ((float4*)out)[idx] = v;
}

// ---------------- host launch ------------------------------------------------------
extern "C" void kernel_launch(void* const* d_in, const int* in_sizes, int n_in,
                              void* d_out, int out_size)
{
    int s = (n_in >= 14 && in_sizes[3] == 1) ? 0 : -1;
    const int*   input    = (const int*)  d_in[0];
    const float* hidden   = (const float*)d_in[1];
    const float* enc      = (const float*)d_in[2];
    const float* emb      = (const float*)d_in[4 + s];
    const float* attn_W   = (const float*)d_in[5 + s];
    const float* attn_b   = (const float*)d_in[6 + s];
    const float* flatten  = (const float*)d_in[7 + s];
    const float* Wih      = (const float*)d_in[8 + s];
    const float* Whh      = (const float*)d_in[9 + s];
    const float* bih      = (const float*)d_in[10 + s];
    const float* bhh      = (const float*)d_in[11 + s];
    const float* outW     = (const float*)d_in[12 + s];
    const float* outb     = (const float*)d_in[13 + s];

    float* dout     = (float*)d_out;
    float* out_h    = (out_size >= B * V + B * H) ? dout + B * V : nullptr;
    float* out_attn = (out_size >= B * V + B * H + B * L) ? dout + B * V + B * H : nullptr;

    k1_prep<<<1, 512>>>(attn_W, attn_b, flatten, hidden, input, emb);

    int smem_kA = (64 * H + H + 64 + 64 + 4) * (int)sizeof(float);  // ~66.8KB
    cudaFuncSetAttribute(kA_attn, cudaFuncAttributeMaxDynamicSharedMemorySize, smem_kA);
    kA_attn<<<B * NCH, 256, smem_kA>>>(enc);

    kB_combine<<<B, 256>>>(out_attn);

    k5_gru<<<768, 256>>>(Wih, Whh, bih, bhh, hidden);
    k6_gates<<<(B * H) / 256, 256>>>(hidden, out_h);

    int smem_k7 = H2 * B * (int)sizeof(float);  // 131072 B
    cudaFuncSetAttribute(k7_logits, cudaFuncAttributeMaxDynamicSharedMemorySize, smem_k7);
    k7_logits<<<V / 128, 256, smem_k7>>>(outW, outb);

    k8m_merge<<<B, 32>>>();
    k8w_write<<<(B * V / 4) / 256, 256>>>(dout);
}